// round 8
// baseline (speedup 1.0000x reference)
#include <cuda_runtime.h>
#include <math.h>

// Shape fixed by reference: [4,1,128,256,256] fp32
#define IMG_W    256
#define IMG_H    256
#define NSLICES  512                  // B*D
#define STRIP_H  32                   // rows per block
#define STRIPS   (IMG_H / STRIP_H)    // 8
#define NB       (NSLICES * STRIPS)   // 4096 blocks
#define YT       2                    // y pair-groups per block
#define NR       (STRIP_H / YT)       // 16 output rows per thread
#define N_TOTAL  (4.0 * 128.0 * 256.0 * 256.0)

__device__ float        g_partials[NB];
__device__ unsigned int g_count = 0;

__device__ __forceinline__ float sqrt_approx(float x) {
    float r; asm("sqrt.approx.f32 %0, %1;" : "=f"(r) : "f"(x)); return r;
}

struct Row6 { float n0, n1, n2, n3, n4, n5; };

// Raw loads only — one aligned float4 + two independent halo scalars
// (L1 hits: same 128B lines as neighboring lanes' vectors). All LDGs
// independent; no shuffles in the load path -> high MLP.
__device__ __forceinline__ Row6 load_row(const float* __restrict__ img,
                                         int row, int cb,
                                         bool row_ok, bool has_l, bool has_r)
{
    Row6 o;
    float4 v = make_float4(0.f, 0.f, 0.f, 0.f);
    float  l = 0.f, r = 0.f;
    if (row_ok) {
        const float* p = img + row * IMG_W + cb;
        v = *reinterpret_cast<const float4*>(p);
        if (has_l) l = p[-1];
        if (has_r) r = p[4];
    }
    o.n0 = l; o.n1 = v.x; o.n2 = v.y; o.n3 = v.z; o.n4 = v.w; o.n5 = r;
    return o;
}

// Separable row aggregates for 4 columns from 6 horizontal values:
//   h1 = r - l        (ex = h1[y-1] + 2h1[y] + h1[y+1])
//   h2 = l + 2m + r   (ey = h2[y+1] - h2[y-1])
__device__ __forceinline__ void row_agg(const Row6& n, float h1[4], float h2[4])
{
    h1[0] = n.n2 - n.n0;  h2[0] = fmaf(2.f, n.n1, n.n0 + n.n2);
    h1[1] = n.n3 - n.n1;  h2[1] = fmaf(2.f, n.n2, n.n1 + n.n3);
    h1[2] = n.n4 - n.n2;  h2[2] = fmaf(2.f, n.n3, n.n2 + n.n4);
    h1[3] = n.n5 - n.n3;  h2[3] = fmaf(2.f, n.n4, n.n3 + n.n5);
}

// Even lanes process pred, odd lanes process target, same 4 columns.
// Cross-image |magp - magt| via shfl_xor(mag, 1) at the chain tail.
__global__ __launch_bounds__(256, 5)
void edge_loss_kernel(const float* __restrict__ pred,
                      const float* __restrict__ target,
                      float* __restrict__ out)
{
    __shared__ float warp_sums[8];
    __shared__ int   s_last;

    const int tid    = threadIdx.x;
    const int imgsel = tid & 1;
    const int pair   = tid >> 1;          // 0..127
    const int x      = pair & 63;         // col group -> cols [4x, 4x+3]
    const int ty     = pair >> 6;         // 0..1
    const int lane   = tid & 31;
    const int cb     = x << 2;
    const bool has_l = (x != 0);
    const bool has_r = (x != 63);

    const int r0 = blockIdx.x * STRIP_H + ty * NR;

    const size_t base = (size_t)blockIdx.y * (IMG_H * IMG_W);
    const float* __restrict__ img = (imgsel ? target : pred) + base;

    float h1p[4], h2p[4], h1c[4], h2c[4];

    // Prologue: rows r0-1 (prev) and r0 (cur), my image only
    {
        Row6 rp = load_row(img, r0 - 1, cb, r0 > 0, has_l, has_r);
        Row6 rc = load_row(img, r0,     cb, true,   has_l, has_r);
        row_agg(rp, h1p, h2p);
        row_agg(rc, h1c, h2c);
    }

    float acc = 0.f;

    #pragma unroll
    for (int i = 0; i < NR; i++) {
        const int  row    = r0 + 1 + i;          // new bottom row
        const bool row_ok = (row < IMG_H);

        const Row6 rn = load_row(img, row, cb, row_ok, has_l, has_r);
        float h1n[4], h2n[4];
        row_agg(rn, h1n, h2n);

        float mag[4];
        #pragma unroll
        for (int j = 0; j < 4; j++) {
            const float ex = fmaf(2.f, h1c[j], h1p[j]) + h1n[j];
            const float ey = h2n[j] - h2p[j];
            mag[j] = sqrt_approx(fmaf(ex, ex, fmaf(ey, ey, 1e-8f)));
        }

        // Pair exchange: partner lane holds the other image's magnitude.
        #pragma unroll
        for (int j = 0; j < 4; j++) {
            const float other = __shfl_xor_sync(0xffffffffu, mag[j], 1);
            acc += fabsf(mag[j] - other);        // both lanes add -> 2x sum
        }

        #pragma unroll
        for (int j = 0; j < 4; j++) {
            h1p[j] = h1c[j]; h1c[j] = h1n[j];
            h2p[j] = h2c[j]; h2c[j] = h2n[j];
        }
    }

    // ---- Deterministic block reduction ----
    #pragma unroll
    for (int off = 16; off > 0; off >>= 1)
        acc += __shfl_down_sync(0xffffffffu, acc, off);
    if (lane == 0) warp_sums[tid >> 5] = acc;
    __syncthreads();

    if (tid == 0) {
        float s = 0.f;
        #pragma unroll
        for (int i = 0; i < 8; i++) s += warp_sums[i];
        g_partials[blockIdx.y * gridDim.x + blockIdx.x] = s;
        __threadfence();
        const unsigned old = atomicAdd(&g_count, 1u);
        s_last = (old == NB - 1) ? 1 : 0;
    }
    __syncthreads();

    // ---- Last block: deterministic final reduce (fixed order, double) ----
    if (s_last) {
        __shared__ double dred[256];
        double s = 0.0;
        #pragma unroll 8
        for (int i = tid; i < NB; i += 256)
            s += (double)g_partials[i];
        dred[tid] = s;
        __syncthreads();
        #pragma unroll
        for (int off = 128; off > 0; off >>= 1) {
            if (tid < off) dred[tid] += dred[tid + off];
            __syncthreads();
        }
        if (tid == 0) {
            out[0]  = (float)(dred[0] / (2.0 * N_TOTAL));  // pairs double-count
            g_count = 0;   // reset for next graph replay
        }
    }
}

extern "C" void kernel_launch(void* const* d_in, const int* in_sizes, int n_in,
                              void* d_out, int out_size)
{
    (void)in_sizes; (void)n_in; (void)out_size;
    const float* pred   = (const float*)d_in[0];
    const float* target = (const float*)d_in[1];
    float* out = (float*)d_out;

    dim3 grid(STRIPS, NSLICES);   // 8 x 512 = 4096 blocks
    edge_loss_kernel<<<grid, 256>>>(pred, target, out);
}

// round 9
// speedup vs baseline: 1.2004x; 1.2004x over previous
#include <cuda_runtime.h>
#include <math.h>

// Shape fixed by reference: [4,1,128,256,256] fp32
#define IMG_W    256
#define IMG_H    256
#define NSLICES  512                  // B*D
#define STRIP_H  32                   // rows per block
#define STRIPS   (IMG_H / STRIP_H)    // 8
#define NB       (NSLICES * STRIPS)   // 4096 blocks
#define YT       2                    // y groups per block (256 thr = 128 x * 2 y)
#define NR       (STRIP_H / YT)       // 16 output rows per thread
#define N_TOTAL  (4.0 * 128.0 * 256.0 * 256.0)

__device__ float        g_partials[NB];
__device__ unsigned int g_count = 0;

__device__ __forceinline__ float sqrt_approx(float x) {
    float r; asm("sqrt.approx.f32 %0, %1;" : "=f"(r) : "f"(x)); return r;
}

struct Row4 { float n0, n1, n2, n3; };   // cols [cb-1, cb, cb+1, cb+2]

// Raw loads only: one aligned float2 + two independent halo scalars
// (L1 hits — same 128B lines as neighboring lanes' vectors).
// No shuffles, no convergence points; all LDGs independent.
__device__ __forceinline__ Row4 load_row2(const float* __restrict__ p,
                                          bool row_ok, bool has_l, bool has_r)
{
    Row4 o;
    float2 v = make_float2(0.f, 0.f);
    float  l = 0.f, r = 0.f;
    if (row_ok) {
        v = *reinterpret_cast<const float2*>(p);
        if (has_l) l = p[-1];
        if (has_r) r = p[2];
    }
    o.n0 = l; o.n1 = v.x; o.n2 = v.y; o.n3 = r;
    return o;
}

// Separable row aggregates for 2 columns:
//   h1 = r - l        (ex = h1[y-1] + 2h1[y] + h1[y+1])
//   h2 = l + 2m + r   (ey = h2[y+1] - h2[y-1])
__device__ __forceinline__ void row_agg2(const Row4& n, float h1[2], float h2[2])
{
    h1[0] = n.n2 - n.n0;  h2[0] = fmaf(2.f, n.n1, n.n0 + n.n2);
    h1[1] = n.n3 - n.n1;  h2[1] = fmaf(2.f, n.n2, n.n1 + n.n3);
}

__global__ __launch_bounds__(256, 5)
void edge_loss_kernel(const float* __restrict__ pred,
                      const float* __restrict__ target,
                      float* __restrict__ out)
{
    __shared__ float warp_sums[8];
    __shared__ int   s_last;

    const int tid  = threadIdx.x;
    const int xt   = tid & 127;           // 0..127 -> cols [2xt, 2xt+1]
    const int ty   = tid >> 7;            // 0..1
    const int lane = tid & 31;
    const int cb   = xt << 1;
    const bool has_l = (xt != 0);
    const bool has_r = (xt != 127);

    const int r0 = blockIdx.x * STRIP_H + ty * NR;

    const size_t base = (size_t)blockIdx.y * (IMG_H * IMG_W);
    const float* __restrict__ P = pred + base + cb;
    const float* __restrict__ T = target + base + cb;

    float ph1p[2], ph2p[2], ph1c[2], ph2c[2];
    float th1p[2], th2p[2], th1c[2], th2c[2];

    // Prologue: rows r0-1 (prev), r0 (cur); prefetch row r0+1 (first body row)
    {
        const Row4 pp = load_row2(P + (r0 - 1) * IMG_W, r0 > 0, has_l, has_r);
        const Row4 tp = load_row2(T + (r0 - 1) * IMG_W, r0 > 0, has_l, has_r);
        const Row4 pc = load_row2(P + r0 * IMG_W, true, has_l, has_r);
        const Row4 tc = load_row2(T + r0 * IMG_W, true, has_l, has_r);
        row_agg2(pp, ph1p, ph2p);
        row_agg2(tp, th1p, th2p);
        row_agg2(pc, ph1c, ph2c);
        row_agg2(tc, th1c, th2c);
    }

    const float* pRow = P + (r0 + 1) * IMG_W;
    const float* tRow = T + (r0 + 1) * IMG_W;
    Row4 pcur = load_row2(pRow, r0 + 1 < IMG_H, has_l, has_r);
    Row4 tcur = load_row2(tRow, r0 + 1 < IMG_H, has_l, has_r);

    float acc = 0.f;

    #pragma unroll
    for (int i = 0; i < NR; i++) {
        // Prefetch row r0+2+i while computing on (pcur, tcur).
        const bool nok = (r0 + 2 + i < IMG_H);
        pRow += IMG_W; tRow += IMG_W;
        const Row4 pnxt = load_row2(pRow, nok, has_l, has_r);
        const Row4 tnxt = load_row2(tRow, nok, has_l, has_r);

        float ph1n[2], ph2n[2], th1n[2], th2n[2];
        row_agg2(pcur, ph1n, ph2n);
        row_agg2(tcur, th1n, th2n);

        #pragma unroll
        for (int j = 0; j < 2; j++) {
            float ex = fmaf(2.f, ph1c[j], ph1p[j]) + ph1n[j];
            float ey = ph2n[j] - ph2p[j];
            const float magp = sqrt_approx(fmaf(ex, ex, fmaf(ey, ey, 1e-8f)));

            ex = fmaf(2.f, th1c[j], th1p[j]) + th1n[j];
            ey = th2n[j] - th2p[j];
            const float magt = sqrt_approx(fmaf(ex, ex, fmaf(ey, ey, 1e-8f)));

            acc += fabsf(magp - magt);
        }

        #pragma unroll
        for (int j = 0; j < 2; j++) {
            ph1p[j] = ph1c[j]; ph1c[j] = ph1n[j];
            ph2p[j] = ph2c[j]; ph2c[j] = ph2n[j];
            th1p[j] = th1c[j]; th1c[j] = th1n[j];
            th2p[j] = th2c[j]; th2c[j] = th2n[j];
        }
        pcur = pnxt; tcur = tnxt;
    }

    // ---- Deterministic block reduction ----
    #pragma unroll
    for (int off = 16; off > 0; off >>= 1)
        acc += __shfl_down_sync(0xffffffffu, acc, off);
    if (lane == 0) warp_sums[tid >> 5] = acc;
    __syncthreads();

    if (tid == 0) {
        float s = 0.f;
        #pragma unroll
        for (int i = 0; i < 8; i++) s += warp_sums[i];
        g_partials[blockIdx.y * gridDim.x + blockIdx.x] = s;
        __threadfence();
        const unsigned old = atomicAdd(&g_count, 1u);
        s_last = (old == NB - 1) ? 1 : 0;
    }
    __syncthreads();

    // ---- Last block: deterministic final reduce (fixed order, double) ----
    if (s_last) {
        __shared__ double dred[256];
        double s = 0.0;
        #pragma unroll 8
        for (int i = tid; i < NB; i += 256)
            s += (double)g_partials[i];
        dred[tid] = s;
        __syncthreads();
        #pragma unroll
        for (int off = 128; off > 0; off >>= 1) {
            if (tid < off) dred[tid] += dred[tid + off];
            __syncthreads();
        }
        if (tid == 0) {
            out[0]  = (float)(dred[0] / N_TOTAL);
            g_count = 0;   // reset for next graph replay
        }
    }
}

extern "C" void kernel_launch(void* const* d_in, const int* in_sizes, int n_in,
                              void* d_out, int out_size)
{
    (void)in_sizes; (void)n_in; (void)out_size;
    const float* pred   = (const float*)d_in[0];
    const float* target = (const float*)d_in[1];
    float* out = (float*)d_out;

    dim3 grid(STRIPS, NSLICES);   // 8 x 512 = 4096 blocks
    edge_loss_kernel<<<grid, 256>>>(pred, target, out);
}